// round 10
// baseline (speedup 1.0000x reference)
#include <cuda_runtime.h>
#include <cuda_bf16.h>
#include <cstdint>
#include <cstddef>

#define NODES 64
#define DIM   256
#define TPB   256
#define PSTR  72    // padded row stride in bf16 elems (144 B, conflict-free ldsm)

// ---------------- device scratch ----------------
// A (=Vs) mma fragments, per-lane layout: idx = mt*512 + ks*128 + lane*4 + q
__device__ __align__(16) uint32_t g_AfHi[2048];
__device__ __align__(16) uint32_t g_AfLo[2048];
__device__ __align__(16) float    g_bsT[4096];      // bsT[n][j] = bs[j][n]
__device__ __align__(16) float    g_lhs[4096 * 64]; // w1 * (x @ W2)
__device__ __align__(16) float    g_rhs[4096 * 64]; // x @ W3

// ---------------- helpers ----------------
__device__ __forceinline__ uint32_t smem_u32(const void* p) {
    uint32_t a;
    asm("{ .reg .u64 t; cvta.to.shared.u64 t, %1; cvt.u32.u64 %0, t; }" : "=r"(a) : "l"(p));
    return a;
}

__device__ __forceinline__ void ldsm_x4(uint32_t& r0, uint32_t& r1,
                                        uint32_t& r2, uint32_t& r3, uint32_t addr) {
    asm volatile("ldmatrix.sync.aligned.m8n8.x4.shared.b16 {%0,%1,%2,%3}, [%4];"
                 : "=r"(r0), "=r"(r1), "=r"(r2), "=r"(r3) : "r"(addr));
}

__device__ __forceinline__ void mma_bf16(float& c0, float& c1, float& c2, float& c3,
                                         uint32_t a0, uint32_t a1, uint32_t a2, uint32_t a3,
                                         uint32_t b0, uint32_t b1) {
    asm volatile(
        "mma.sync.aligned.m16n8k16.row.col.f32.bf16.bf16.f32 "
        "{%0,%1,%2,%3}, {%4,%5,%6,%7}, {%8,%9}, {%0,%1,%2,%3};"
        : "+f"(c0), "+f"(c1), "+f"(c2), "+f"(c3)
        : "r"(a0), "r"(a1), "r"(a2), "r"(a3), "r"(b0), "r"(b1));
}

__device__ __forceinline__ float fast_tanh(float v) {
    float e = __expf(2.0f * v);
    return 1.0f - __fdividef(2.0f, e + 1.0f);
}

__device__ __forceinline__ uint32_t pack_hi(float v0, float v1,
                                            float& r0, float& r1) {
    __nv_bfloat16 h0 = __float2bfloat16(v0);
    __nv_bfloat16 h1 = __float2bfloat16(v1);
    r0 = v0 - __bfloat162float(h0);
    r1 = v1 - __bfloat162float(h1);
    return (uint32_t)__bfloat16_as_ushort(h0)
         | ((uint32_t)__bfloat16_as_ushort(h1) << 16);
}
__device__ __forceinline__ uint32_t pack_lo(float r0, float r1) {
    return (uint32_t)__bfloat16_as_ushort(__float2bfloat16(r0))
         | ((uint32_t)__bfloat16_as_ushort(__float2bfloat16(r1)) << 16);
}

// merge-tree warp reduce of 8 per-lane partial sets -> per-lane row total.
// Row for lane l: R = 4*b2 + 2*b3 + b4
__device__ __forceinline__ float reduce8(float v[8], int lane) {
    float m[4];
    #pragma unroll
    for (int p = 0; p < 4; p++) {
        float s = (lane & 16) ? v[2 * p]     : v[2 * p + 1];
        float k = (lane & 16) ? v[2 * p + 1] : v[2 * p];
        m[p] = k + __shfl_xor_sync(0xffffffffu, s, 16);
    }
    float n[2];
    #pragma unroll
    for (int p = 0; p < 2; p++) {
        float s = (lane & 8) ? m[2 * p]     : m[2 * p + 1];
        float k = (lane & 8) ? m[2 * p + 1] : m[2 * p];
        n[p] = k + __shfl_xor_sync(0xffffffffu, s, 8);
    }
    float s = (lane & 4) ? n[0] : n[1];
    float k = (lane & 4) ? n[1] : n[0];
    float o = k + __shfl_xor_sync(0xffffffffu, s, 4);
    o += __shfl_xor_sync(0xffffffffu, o, 2);
    o += __shfl_xor_sync(0xffffffffu, o, 1);
    return o;
}

// ---------------- precompute: A mma fragments (hi/lo) + bsT ----------------
__global__ void precompute_kernel(const float* __restrict__ bs,
                                  const float* __restrict__ Vs) {
    int e = blockIdx.x * blockDim.x + threadIdx.x;   // 0..4095
    if (e < 2048) {
        int mt = e >> 9, ks = (e >> 7) & 3, lane = (e >> 2) & 31, q = e & 3;
        int row = 16 * mt + (lane >> 2) + (q & 1) * 8;
        int col = 16 * ks + (lane & 3) * 2 + ((q >> 1) & 1) * 8;
        float v0 = Vs[row * 64 + col];
        float v1 = Vs[row * 64 + col + 1];
        float r0, r1;
        uint32_t hw = pack_hi(v0, v1, r0, r1);
        g_AfHi[e] = hw;
        g_AfLo[e] = pack_lo(r0, r1);
    }
    {
        int i = e >> 6, j = e & 63;
        g_bsT[e] = bs[j * 64 + i];
    }
}

// ---------------- K1: streaming GEMV, lhs/rhs for all batches ----------------
__global__ __launch_bounds__(TPB, 4)
void lhs_rhs_kernel(const float* __restrict__ x,
                    const float* __restrict__ W1,
                    const float* __restrict__ W2,
                    const float* __restrict__ W3) {
    const int tid  = threadIdx.x;
    const int lane = tid & 31;
    const int w    = tid >> 5;

    const float w1   = *W1;
    const float4 w2a = *(const float4*)(W2 + 4 * lane);
    const float4 w2b = *(const float4*)(W2 + 128 + 4 * lane);
    const float4 w3a = *(const float4*)(W3 + 4 * lane);
    const float4 w3b = *(const float4*)(W3 + 128 + 4 * lane);
    const float* xb  = x + (size_t)blockIdx.x * (NODES * DIM);

    float a2[8], a3[8];
    #pragma unroll
    for (int r = 0; r < 8; r++) {
        const float* xr = xb + ((w << 3) + r) * DIM;
        float4 u = *(const float4*)(xr + (lane << 2));
        float4 v = *(const float4*)(xr + 128 + (lane << 2));
        a2[r] = u.x * w2a.x + u.y * w2a.y + u.z * w2a.z + u.w * w2a.w
              + v.x * w2b.x + v.y * w2b.y + v.z * w2b.z + v.w * w2b.w;
        a3[r] = u.x * w3a.x + u.y * w3a.y + u.z * w3a.z + u.w * w3a.w
              + v.x * w3b.x + v.y * w3b.y + v.z * w3b.z + v.w * w3b.w;
    }
    float s2 = reduce8(a2, lane);
    float s3 = reduce8(a3, lane);
    if ((lane & 3) == 0) {
        int R = 4 * ((lane >> 2) & 1) + 2 * ((lane >> 3) & 1) + ((lane >> 4) & 1);
        int idx = blockIdx.x * NODES + (w << 3) + R;
        g_lhs[idx] = w1 * s2;
        g_rhs[idx] = s3;
    }
}

// ---------------- K2: t-build + bf16x3 MMA GEMM + softmax + store ----------------
__global__ __launch_bounds__(TPB, 4)
void adj_attn_mma(float* __restrict__ out) {
    __shared__ __align__(16) __nv_bfloat16 tHiS[64 * PSTR];   // tT[n][j] hi
    __shared__ __align__(16) __nv_bfloat16 tLoS[64 * PSTR];   // tT[n][j] lo
    __shared__ float lhsS[NODES];
    __shared__ float rhsS[NODES];
    __shared__ float redS[16];

    const int tid  = threadIdx.x;
    const int lane = tid & 31;
    const int w    = tid >> 5;

    // ---- load lhs/rhs for this batch (L2-resident scratch) ----
    if (tid < 64)       lhsS[tid]      = g_lhs[blockIdx.x * NODES + tid];
    else if (tid < 128) rhsS[tid - 64] = g_rhs[blockIdx.x * NODES + tid - 64];
    __syncthreads();

    // ---- build tT[n][j] = tanh(lhs[j]*rhs[n] + bsT[n][j]) as bf16 hi/lo ----
    {
        const int n  = tid >> 2;
        const int j0 = (tid & 3) * 16;
        const float rv = rhsS[n];
        #pragma unroll
        for (int c = 0; c < 2; c++) {
            const int j = j0 + c * 8;
            float4 l0 = *(const float4*)(lhsS + j);
            float4 l1 = *(const float4*)(lhsS + j + 4);
            float4 b0 = *(const float4*)(g_bsT + n * 64 + j);
            float4 b1 = *(const float4*)(g_bsT + n * 64 + j + 4);
            float tv[8];
            tv[0] = fast_tanh(fmaf(l0.x, rv, b0.x));
            tv[1] = fast_tanh(fmaf(l0.y, rv, b0.y));
            tv[2] = fast_tanh(fmaf(l0.z, rv, b0.z));
            tv[3] = fast_tanh(fmaf(l0.w, rv, b0.w));
            tv[4] = fast_tanh(fmaf(l1.x, rv, b1.x));
            tv[5] = fast_tanh(fmaf(l1.y, rv, b1.y));
            tv[6] = fast_tanh(fmaf(l1.z, rv, b1.z));
            tv[7] = fast_tanh(fmaf(l1.w, rv, b1.w));
            uint4 hw, lw;
            float r0, r1;
            hw.x = pack_hi(tv[0], tv[1], r0, r1); lw.x = pack_lo(r0, r1);
            hw.y = pack_hi(tv[2], tv[3], r0, r1); lw.y = pack_lo(r0, r1);
            hw.z = pack_hi(tv[4], tv[5], r0, r1); lw.z = pack_lo(r0, r1);
            hw.w = pack_hi(tv[6], tv[7], r0, r1); lw.w = pack_lo(r0, r1);
            *(uint4*)((char*)tHiS + (n * PSTR + j) * 2) = hw;
            *(uint4*)((char*)tLoS + (n * PSTR + j) * 2) = lw;
        }
    }
    __syncthreads();

    // ---- warp-level GEMM: warp w -> rows 16*(w>>1).., cols 32*(w&1).. ----
    const int mt = w >> 1;
    const int nh = w & 1;

    const uint32_t sTHi = smem_u32(tHiS);
    const uint32_t sTLo = smem_u32(tLoS);

    const uint32_t bOff0 = (uint32_t)(((nh * 32 + (lane & 7) + ((lane >> 4) & 1) * 8) * PSTR
                                       + ((lane >> 3) & 1) * 8) * 2);
    const uint32_t bOff1 = bOff0 + (uint32_t)(16 * PSTR * 2);

    float acc[16];
    #pragma unroll
    for (int i = 0; i < 16; i++) acc[i] = 0.0f;

    const uint4* fHi = (const uint4*)g_AfHi;   // [(mt*4+ks)*32 + lane]
    const uint4* fLo = (const uint4*)g_AfLo;

    #pragma unroll
    for (int ks = 0; ks < 4; ks++) {
        const int fidx = (mt * 4 + ks) * 32 + lane;
        uint4 ah = fHi[fidx];
        uint4 al = fLo[fidx];
        const uint32_t joff = (uint32_t)(ks * 32);
        uint32_t bh0, bh1, bh2, bh3, bh4, bh5, bh6, bh7;
        uint32_t bl0, bl1, bl2, bl3, bl4, bl5, bl6, bl7;
        ldsm_x4(bh0, bh1, bh2, bh3, sTHi + bOff0 + joff);
        ldsm_x4(bh4, bh5, bh6, bh7, sTHi + bOff1 + joff);
        ldsm_x4(bl0, bl1, bl2, bl3, sTLo + bOff0 + joff);
        ldsm_x4(bl4, bl5, bl6, bl7, sTLo + bOff1 + joff);
        // Ah*Bh
        mma_bf16(acc[0],  acc[1],  acc[2],  acc[3],  ah.x, ah.y, ah.z, ah.w, bh0, bh1);
        mma_bf16(acc[4],  acc[5],  acc[6],  acc[7],  ah.x, ah.y, ah.z, ah.w, bh2, bh3);
        mma_bf16(acc[8],  acc[9],  acc[10], acc[11], ah.x, ah.y, ah.z, ah.w, bh4, bh5);
        mma_bf16(acc[12], acc[13], acc[14], acc[15], ah.x, ah.y, ah.z, ah.w, bh6, bh7);
        // Ah*Bl
        mma_bf16(acc[0],  acc[1],  acc[2],  acc[3],  ah.x, ah.y, ah.z, ah.w, bl0, bl1);
        mma_bf16(acc[4],  acc[5],  acc[6],  acc[7],  ah.x, ah.y, ah.z, ah.w, bl2, bl3);
        mma_bf16(acc[8],  acc[9],  acc[10], acc[11], ah.x, ah.y, ah.z, ah.w, bl4, bl5);
        mma_bf16(acc[12], acc[13], acc[14], acc[15], ah.x, ah.y, ah.z, ah.w, bl6, bl7);
        // Al*Bh
        mma_bf16(acc[0],  acc[1],  acc[2],  acc[3],  al.x, al.y, al.z, al.w, bh0, bh1);
        mma_bf16(acc[4],  acc[5],  acc[6],  acc[7],  al.x, al.y, al.z, al.w, bh2, bh3);
        mma_bf16(acc[8],  acc[9],  acc[10], acc[11], al.x, al.y, al.z, al.w, bh4, bh5);
        mma_bf16(acc[12], acc[13], acc[14], acc[15], al.x, al.y, al.z, al.w, bh6, bh7);
    }

    // ---- softmax over all 4096 scores of this batch element ----
    float m = acc[0];
    #pragma unroll
    for (int i = 1; i < 16; i++) m = fmaxf(m, acc[i]);
    #pragma unroll
    for (int sft = 16; sft > 0; sft >>= 1)
        m = fmaxf(m, __shfl_xor_sync(0xffffffffu, m, sft));
    if (lane == 0) redS[w] = m;
    __syncthreads();
    float bm = redS[0];
    #pragma unroll
    for (int i = 1; i < 8; i++) bm = fmaxf(bm, redS[i]);

    float lsum = 0.0f;
    #pragma unroll
    for (int i = 0; i < 16; i++) {
        acc[i] = __expf(acc[i] - bm);
        lsum += acc[i];
    }
    #pragma unroll
    for (int sft = 16; sft > 0; sft >>= 1)
        lsum += __shfl_xor_sync(0xffffffffu, lsum, sft);
    if (lane == 0) redS[8 + w] = lsum;
    __syncthreads();
    float tot = redS[8];
    #pragma unroll
    for (int i = 1; i < 8; i++) tot += redS[8 + i];
    const float inv = 1.0f / tot;

    // ---- store: rows {16mt+lane/4, +8}, cols 32nh + g*8 + (lane%4)*2 ----
    float* ob = out + (size_t)blockIdx.x * (NODES * NODES);
    const int row0 = 16 * mt + (lane >> 2);
    const int col0 = 32 * nh + (lane & 3) * 2;
    #pragma unroll
    for (int g = 0; g < 4; g++) {
        float2 o;
        o.x = acc[g * 4 + 0] * inv;
        o.y = acc[g * 4 + 1] * inv;
        *(float2*)(ob + row0 * NODES + col0 + g * 8) = o;
        o.x = acc[g * 4 + 2] * inv;
        o.y = acc[g * 4 + 3] * inv;
        *(float2*)(ob + (row0 + 8) * NODES + col0 + g * 8) = o;
    }
}

extern "C" void kernel_launch(void* const* d_in, const int* in_sizes, int n_in,
                              void* d_out, int out_size) {
    const float* x  = (const float*)d_in[0];
    const float* W1 = (const float*)d_in[1];
    const float* W2 = (const float*)d_in[2];
    const float* W3 = (const float*)d_in[3];
    const float* bs = (const float*)d_in[4];
    const float* Vs = (const float*)d_in[5];
    float* out = (float*)d_out;

    const int B = in_sizes[0] / (NODES * DIM);   // 4096
    precompute_kernel<<<16, 256>>>(bs, Vs);
    lhs_rhs_kernel<<<B, TPB>>>(x, W1, W2, W3);
    adj_attn_mma<<<B, TPB>>>(out);
}

// round 11
// speedup vs baseline: 1.1414x; 1.1414x over previous
#include <cuda_runtime.h>
#include <cuda_bf16.h>
#include <cstdint>
#include <cstddef>

#define NODES 64
#define DIM   256
#define TPB   256
#define PSTR  72    // padded row stride in bf16 elems (144 B, conflict-free ldsm)

// ---------------- device scratch (grid-constant precompute) ----------------
// A (=Vs) mma fragments, per-lane layout: idx = (mt*4+ks)*32*4 + lane*4 + q  (as uint32)
__device__ __align__(16) uint32_t g_AfHi[2048];
__device__ __align__(16) uint32_t g_AfLo[2048];
__device__ __align__(16) float    g_bsT[4096];    // bsT[n][j] = bs[j][n]

// ---------------- helpers ----------------
__device__ __forceinline__ uint32_t smem_u32(const void* p) {
    uint32_t a;
    asm("{ .reg .u64 t; cvta.to.shared.u64 t, %1; cvt.u32.u64 %0, t; }" : "=r"(a) : "l"(p));
    return a;
}

__device__ __forceinline__ void ldsm_x4(uint32_t& r0, uint32_t& r1,
                                        uint32_t& r2, uint32_t& r3, uint32_t addr) {
    asm volatile("ldmatrix.sync.aligned.m8n8.x4.shared.b16 {%0,%1,%2,%3}, [%4];"
                 : "=r"(r0), "=r"(r1), "=r"(r2), "=r"(r3) : "r"(addr));
}

__device__ __forceinline__ void mma_bf16(float& c0, float& c1, float& c2, float& c3,
                                         uint32_t a0, uint32_t a1, uint32_t a2, uint32_t a3,
                                         uint32_t b0, uint32_t b1) {
    asm volatile(
        "mma.sync.aligned.m16n8k16.row.col.f32.bf16.bf16.f32 "
        "{%0,%1,%2,%3}, {%4,%5,%6,%7}, {%8,%9}, {%0,%1,%2,%3};"
        : "+f"(c0), "+f"(c1), "+f"(c2), "+f"(c3)
        : "r"(a0), "r"(a1), "r"(a2), "r"(a3), "r"(b0), "r"(b1));
}

__device__ __forceinline__ float fast_tanh(float v) {
    float e = __expf(2.0f * v);
    return 1.0f - __fdividef(2.0f, e + 1.0f);
}

__device__ __forceinline__ uint32_t pack_hi(float v0, float v1,
                                            float& r0, float& r1) {
    __nv_bfloat16 h0 = __float2bfloat16(v0);
    __nv_bfloat16 h1 = __float2bfloat16(v1);
    r0 = v0 - __bfloat162float(h0);
    r1 = v1 - __bfloat162float(h1);
    return (uint32_t)__bfloat16_as_ushort(h0)
         | ((uint32_t)__bfloat16_as_ushort(h1) << 16);
}
__device__ __forceinline__ uint32_t pack_lo(float r0, float r1) {
    return (uint32_t)__bfloat16_as_ushort(__float2bfloat16(r0))
         | ((uint32_t)__bfloat16_as_ushort(__float2bfloat16(r1)) << 16);
}

// merge-tree warp reduce of 8 per-lane partial sets -> per-lane row total.
// Row for lane l: R = 4*b2 + 2*b3 + b4
__device__ __forceinline__ float reduce8(float v[8], int lane) {
    float m[4];
    #pragma unroll
    for (int p = 0; p < 4; p++) {
        float s = (lane & 16) ? v[2 * p]     : v[2 * p + 1];
        float k = (lane & 16) ? v[2 * p + 1] : v[2 * p];
        m[p] = k + __shfl_xor_sync(0xffffffffu, s, 16);
    }
    float n[2];
    #pragma unroll
    for (int p = 0; p < 2; p++) {
        float s = (lane & 8) ? m[2 * p]     : m[2 * p + 1];
        float k = (lane & 8) ? m[2 * p + 1] : m[2 * p];
        n[p] = k + __shfl_xor_sync(0xffffffffu, s, 8);
    }
    float s = (lane & 4) ? n[0] : n[1];
    float k = (lane & 4) ? n[1] : n[0];
    float o = k + __shfl_xor_sync(0xffffffffu, s, 4);
    o += __shfl_xor_sync(0xffffffffu, o, 2);
    o += __shfl_xor_sync(0xffffffffu, o, 1);
    return o;
}

// ---------------- precompute: A mma fragments (hi/lo) + bsT ----------------
__global__ void precompute_kernel(const float* __restrict__ bs,
                                  const float* __restrict__ Vs) {
    int e = blockIdx.x * blockDim.x + threadIdx.x;   // 0..4095
    if (e < 2048) {
        int mt = e >> 9, ks = (e >> 7) & 3, lane = (e >> 2) & 31, q = e & 3;
        int row = 16 * mt + (lane >> 2) + (q & 1) * 8;
        int col = 16 * ks + (lane & 3) * 2 + ((q >> 1) & 1) * 8;
        float v0 = Vs[row * 64 + col];
        float v1 = Vs[row * 64 + col + 1];
        float r0, r1;
        uint32_t hw = pack_hi(v0, v1, r0, r1);
        g_AfHi[e] = hw;
        g_AfLo[e] = pack_lo(r0, r1);
    }
    {
        int i = e >> 6, j = e & 63;
        g_bsT[e] = bs[j * 64 + i];
    }
}

// ---------------- fused kernel: 2 batch elements per block ----------------
__global__ __launch_bounds__(TPB, 3)
void adj_attn_mma(const float* __restrict__ x,
                  const float* __restrict__ W1,
                  const float* __restrict__ W2,
                  const float* __restrict__ W3,
                  float* __restrict__ out) {
    __shared__ __align__(16) __nv_bfloat16 tHiS[2][64 * PSTR];  // tT[n][j] hi per batch
    __shared__ __align__(16) __nv_bfloat16 tLoS[2][64 * PSTR];  // tT[n][j] lo per batch
    __shared__ float lhsS[2][NODES];
    __shared__ float rhsS[2][NODES];
    __shared__ float redS[8];

    const int tid  = threadIdx.x;
    const int lane = tid & 31;
    const int w    = tid >> 5;
    const int bloc = w >> 2;     // batch slot (0/1)
    const int wb   = w & 3;      // warp within batch

    // ---- x-phase: warp handles 16 rows of its batch in 2 passes of 8 ----
    const float w1   = *W1;
    const float4 w2a = *(const float4*)(W2 + 4 * lane);
    const float4 w2b = *(const float4*)(W2 + 128 + 4 * lane);
    const float4 w3a = *(const float4*)(W3 + 4 * lane);
    const float4 w3b = *(const float4*)(W3 + 128 + 4 * lane);
    const float* xb  = x + ((size_t)blockIdx.x * 2 + bloc) * (NODES * DIM);

    #pragma unroll
    for (int pass = 0; pass < 2; pass++) {
        const int rbase = wb * 16 + pass * 8;
        float a2[8], a3[8];
        #pragma unroll
        for (int r = 0; r < 8; r++) {
            const float* xr = xb + (rbase + r) * DIM;
            float4 u = *(const float4*)(xr + (lane << 2));
            float4 v = *(const float4*)(xr + 128 + (lane << 2));
            a2[r] = u.x * w2a.x + u.y * w2a.y + u.z * w2a.z + u.w * w2a.w
                  + v.x * w2b.x + v.y * w2b.y + v.z * w2b.z + v.w * w2b.w;
            a3[r] = u.x * w3a.x + u.y * w3a.y + u.z * w3a.z + u.w * w3a.w
                  + v.x * w3b.x + v.y * w3b.y + v.z * w3b.z + v.w * w3b.w;
        }
        float s2 = reduce8(a2, lane);
        float s3 = reduce8(a3, lane);
        if ((lane & 3) == 0) {
            int R = 4 * ((lane >> 2) & 1) + 2 * ((lane >> 3) & 1) + ((lane >> 4) & 1);
            lhsS[bloc][rbase + R] = w1 * s2;
            rhsS[bloc][rbase + R] = s3;
        }
    }
    __syncthreads();

    // ---- build tT[n][j] = tanh(lhs[j]*rhs[n] + bsT[n][j]) as bf16 hi/lo ----
    {
        const int rowid = tid >> 1;          // 0..127: batch = rowid>>6, n = rowid&63
        const int b2    = rowid >> 6;
        const int n     = rowid & 63;
        const int jh    = (tid & 1) * 32;
        const float rv  = rhsS[b2][n];
        const float* bsr = g_bsT + n * 64 + jh;
        const float* lr  = &lhsS[b2][jh];

        #pragma unroll
        for (int jc = 0; jc < 4; jc++) {      // 8 j per chunk
            float4 l0 = *(const float4*)(lr + jc * 8);
            float4 l1 = *(const float4*)(lr + jc * 8 + 4);
            float4 b0 = *(const float4*)(bsr + jc * 8);
            float4 b1 = *(const float4*)(bsr + jc * 8 + 4);
            float tv[8];
            tv[0] = fast_tanh(fmaf(l0.x, rv, b0.x));
            tv[1] = fast_tanh(fmaf(l0.y, rv, b0.y));
            tv[2] = fast_tanh(fmaf(l0.z, rv, b0.z));
            tv[3] = fast_tanh(fmaf(l0.w, rv, b0.w));
            tv[4] = fast_tanh(fmaf(l1.x, rv, b1.x));
            tv[5] = fast_tanh(fmaf(l1.y, rv, b1.y));
            tv[6] = fast_tanh(fmaf(l1.z, rv, b1.z));
            tv[7] = fast_tanh(fmaf(l1.w, rv, b1.w));
            uint4 hw, lw;
            float r0, r1;
            hw.x = pack_hi(tv[0], tv[1], r0, r1); lw.x = pack_lo(r0, r1);
            hw.y = pack_hi(tv[2], tv[3], r0, r1); lw.y = pack_lo(r0, r1);
            hw.z = pack_hi(tv[4], tv[5], r0, r1); lw.z = pack_lo(r0, r1);
            hw.w = pack_hi(tv[6], tv[7], r0, r1); lw.w = pack_lo(r0, r1);
            const int j = jh + jc * 8;
            *(uint4*)((char*)&tHiS[b2][0] + (n * PSTR + j) * 2) = hw;
            *(uint4*)((char*)&tLoS[b2][0] + (n * PSTR + j) * 2) = lw;
        }
    }
    __syncthreads();

    // ---- GEMM: warp w -> batch bloc, rows 32*(wb>>1).., cols 32*(wb&1).. ----
    const int mrow = wb >> 1;    // 32-row group
    const int nh   = wb & 1;     // 32-col group

    const uint32_t sTHi = smem_u32(&tHiS[bloc][0]);
    const uint32_t sTLo = smem_u32(&tLoS[bloc][0]);

    const uint32_t bOff0 = (uint32_t)(((nh * 32 + (lane & 7) + ((lane >> 4) & 1) * 8) * PSTR
                                       + ((lane >> 3) & 1) * 8) * 2);
    const uint32_t bOff1 = bOff0 + (uint32_t)(16 * PSTR * 2);

    float acc[32];               // [mi*16 + g*4 + c]: mi = m16 tile, g = n8 tile
    #pragma unroll
    for (int i = 0; i < 32; i++) acc[i] = 0.0f;

    const uint4* fHi = (const uint4*)g_AfHi;   // [(mt*4+ks)*32 + lane]
    const uint4* fLo = (const uint4*)g_AfLo;

    #pragma unroll
    for (int ks = 0; ks < 4; ks++) {
        const int mt0 = 2 * mrow;
        uint4 ah0 = fHi[(mt0 * 4 + ks) * 32 + lane];
        uint4 al0 = fLo[(mt0 * 4 + ks) * 32 + lane];
        uint4 ah1 = fHi[((mt0 + 1) * 4 + ks) * 32 + lane];
        uint4 al1 = fLo[((mt0 + 1) * 4 + ks) * 32 + lane];
        const uint32_t joff = (uint32_t)(ks * 32);
        uint32_t bh0, bh1, bh2, bh3, bh4, bh5, bh6, bh7;
        uint32_t bl0, bl1, bl2, bl3, bl4, bl5, bl6, bl7;
        ldsm_x4(bh0, bh1, bh2, bh3, sTHi + bOff0 + joff);
        ldsm_x4(bh4, bh5, bh6, bh7, sTHi + bOff1 + joff);
        ldsm_x4(bl0, bl1, bl2, bl3, sTLo + bOff0 + joff);
        ldsm_x4(bl4, bl5, bl6, bl7, sTLo + bOff1 + joff);

        // ---- m-tile 0 ----
        mma_bf16(acc[0],  acc[1],  acc[2],  acc[3],  ah0.x, ah0.y, ah0.z, ah0.w, bh0, bh1);
        mma_bf16(acc[4],  acc[5],  acc[6],  acc[7],  ah0.x, ah0.y, ah0.z, ah0.w, bh2, bh3);
        mma_bf16(acc[8],  acc[9],  acc[10], acc[11], ah0.x, ah0.y, ah0.z, ah0.w, bh4, bh5);
        mma_bf16(acc[12], acc[13], acc[14], acc[15], ah0.x, ah0.y, ah0.z, ah0.w, bh6, bh7);
        mma_bf16(acc[0],  acc[1],  acc[2],  acc[3],  ah0.x, ah0.y, ah0.z, ah0.w, bl0, bl1);
        mma_bf16(acc[4],  acc[5],  acc[6],  acc[7],  ah0.x, ah0.y, ah0.z, ah0.w, bl2, bl3);
        mma_bf16(acc[8],  acc[9],  acc[10], acc[11], ah0.x, ah0.y, ah0.z, ah0.w, bl4, bl5);
        mma_bf16(acc[12], acc[13], acc[14], acc[15], ah0.x, ah0.y, ah0.z, ah0.w, bl6, bl7);
        mma_bf16(acc[0],  acc[1],  acc[2],  acc[3],  al0.x, al0.y, al0.z, al0.w, bh0, bh1);
        mma_bf16(acc[4],  acc[5],  acc[6],  acc[7],  al0.x, al0.y, al0.z, al0.w, bh2, bh3);
        mma_bf16(acc[8],  acc[9],  acc[10], acc[11], al0.x, al0.y, al0.z, al0.w, bh4, bh5);
        mma_bf16(acc[12], acc[13], acc[14], acc[15], al0.x, al0.y, al0.z, al0.w, bh6, bh7);

        // ---- m-tile 1 (reuses the same B fragments) ----
        mma_bf16(acc[16], acc[17], acc[18], acc[19], ah1.x, ah1.y, ah1.z, ah1.w, bh0, bh1);
        mma_bf16(acc[20], acc[21], acc[22], acc[23], ah1.x, ah1.y, ah1.z, ah1.w, bh2, bh3);
        mma_bf16(acc[24], acc[25], acc[26], acc[27], ah1.x, ah1.y, ah1.z, ah1.w, bh4, bh5);
        mma_bf16(acc[28], acc[29], acc[30], acc[31], ah1.x, ah1.y, ah1.z, ah1.w, bh6, bh7);
        mma_bf16(acc[16], acc[17], acc[18], acc[19], ah1.x, ah1.y, ah1.z, ah1.w, bl0, bl1);
        mma_bf16(acc[20], acc[21], acc[22], acc[23], ah1.x, ah1.y, ah1.z, ah1.w, bl2, bl3);
        mma_bf16(acc[24], acc[25], acc[26], acc[27], ah1.x, ah1.y, ah1.z, ah1.w, bl4, bl5);
        mma_bf16(acc[28], acc[29], acc[30], acc[31], ah1.x, ah1.y, ah1.z, ah1.w, bl6, bl7);
        mma_bf16(acc[16], acc[17], acc[18], acc[19], al1.x, al1.y, al1.z, al1.w, bh0, bh1);
        mma_bf16(acc[20], acc[21], acc[22], acc[23], al1.x, al1.y, al1.z, al1.w, bh2, bh3);
        mma_bf16(acc[24], acc[25], acc[26], acc[27], al1.x, al1.y, al1.z, al1.w, bh4, bh5);
        mma_bf16(acc[28], acc[29], acc[30], acc[31], al1.x, al1.y, al1.z, al1.w, bh6, bh7);
    }

    // ---- softmax (no max subtraction: |s| bounded ~76, exp stays finite) ----
    float lsum = 0.0f;
    #pragma unroll
    for (int i = 0; i < 32; i++) {
        acc[i] = __expf(acc[i]);
        lsum += acc[i];
    }
    #pragma unroll
    for (int sft = 16; sft > 0; sft >>= 1)
        lsum += __shfl_xor_sync(0xffffffffu, lsum, sft);
    if (lane == 0) redS[w] = lsum;
    __syncthreads();
    const float tot = redS[4 * bloc] + redS[4 * bloc + 1]
                    + redS[4 * bloc + 2] + redS[4 * bloc + 3];
    const float inv = 1.0f / tot;

    // ---- store: per m-tile rows {32mrow+16mi+lane/4, +8}, cols 32nh+g*8+(lane%4)*2 ----
    float* ob = out + ((size_t)blockIdx.x * 2 + bloc) * (NODES * NODES);
    const int col0 = 32 * nh + (lane & 3) * 2;
    #pragma unroll
    for (int mi = 0; mi < 2; mi++) {
        const int row0 = 32 * mrow + 16 * mi + (lane >> 2);
        #pragma unroll
        for (int g = 0; g < 4; g++) {
            float2 o;
            o.x = acc[mi * 16 + g * 4 + 0] * inv;
            o.y = acc[mi * 16 + g * 4 + 1] * inv;
            *(float2*)(ob + row0 * NODES + col0 + g * 8) = o;
            o.x = acc[mi * 16 + g * 4 + 2] * inv;
            o.y = acc[mi * 16 + g * 4 + 3] * inv;
            *(float2*)(ob + (row0 + 8) * NODES + col0 + g * 8) = o;
        }
    }
}

extern "C" void kernel_launch(void* const* d_in, const int* in_sizes, int n_in,
                              void* d_out, int out_size) {
    const float* x  = (const float*)d_in[0];
    const float* W1 = (const float*)d_in[1];
    const float* W2 = (const float*)d_in[2];
    const float* W3 = (const float*)d_in[3];
    const float* bs = (const float*)d_in[4];
    const float* Vs = (const float*)d_in[5];
    float* out = (float*)d_out;

    const int B = in_sizes[0] / (NODES * DIM);   // 4096
    precompute_kernel<<<16, 256>>>(bs, Vs);
    adj_attn_mma<<<B / 2, TPB>>>(x, W1, W2, W3, out);
}

// round 12
// speedup vs baseline: 1.3645x; 1.1955x over previous
#include <cuda_runtime.h>
#include <cuda_bf16.h>
#include <cstdint>
#include <cstddef>

#define NODES 64
#define DIM   256
#define TPB   256
#define PSTR  72    // padded row stride in bf16 elems (144 B, conflict-free ldsm)

// ---------------- device scratch (grid-constant precompute) ----------------
// A (=Vs) mma fragments, per-lane layout: idx = (mt*4+ks)*128 + lane*4 + q
__device__ __align__(16) uint32_t g_AfHi[2048];
__device__ __align__(16) uint32_t g_AfLo[2048];
__device__ __align__(16) float    g_bsT[4096];    // bsT[n][j] = bs[j][n]

// ---------------- helpers ----------------
__device__ __forceinline__ uint32_t smem_u32(const void* p) {
    uint32_t a;
    asm("{ .reg .u64 t; cvta.to.shared.u64 t, %1; cvt.u32.u64 %0, t; }" : "=r"(a) : "l"(p));
    return a;
}

__device__ __forceinline__ void ldsm_x4(uint32_t& r0, uint32_t& r1,
                                        uint32_t& r2, uint32_t& r3, uint32_t addr) {
    asm volatile("ldmatrix.sync.aligned.m8n8.x4.shared.b16 {%0,%1,%2,%3}, [%4];"
                 : "=r"(r0), "=r"(r1), "=r"(r2), "=r"(r3) : "r"(addr));
}

__device__ __forceinline__ void mma_bf16(float& c0, float& c1, float& c2, float& c3,
                                         uint32_t a0, uint32_t a1, uint32_t a2, uint32_t a3,
                                         uint32_t b0, uint32_t b1) {
    asm volatile(
        "mma.sync.aligned.m16n8k16.row.col.f32.bf16.bf16.f32 "
        "{%0,%1,%2,%3}, {%4,%5,%6,%7}, {%8,%9}, {%0,%1,%2,%3};"
        : "+f"(c0), "+f"(c1), "+f"(c2), "+f"(c3)
        : "r"(a0), "r"(a1), "r"(a2), "r"(a3), "r"(b0), "r"(b1));
}

__device__ __forceinline__ float fast_tanh(float v) {
    float e = __expf(2.0f * v);
    return 1.0f - __fdividef(2.0f, e + 1.0f);
}

__device__ __forceinline__ uint32_t pack_hi(float v0, float v1,
                                            float& r0, float& r1) {
    __nv_bfloat16 h0 = __float2bfloat16(v0);
    __nv_bfloat16 h1 = __float2bfloat16(v1);
    r0 = v0 - __bfloat162float(h0);
    r1 = v1 - __bfloat162float(h1);
    return (uint32_t)__bfloat16_as_ushort(h0)
         | ((uint32_t)__bfloat16_as_ushort(h1) << 16);
}
__device__ __forceinline__ uint32_t pack_lo(float r0, float r1) {
    return (uint32_t)__bfloat16_as_ushort(__float2bfloat16(r0))
         | ((uint32_t)__bfloat16_as_ushort(__float2bfloat16(r1)) << 16);
}

// merge-tree warp reduce of 8 per-lane partial sets -> per-lane row total.
// Row for lane l: R = 4*b2 + 2*b3 + b4
__device__ __forceinline__ float reduce8(float v[8], int lane) {
    float m[4];
    #pragma unroll
    for (int p = 0; p < 4; p++) {
        float s = (lane & 16) ? v[2 * p]     : v[2 * p + 1];
        float k = (lane & 16) ? v[2 * p + 1] : v[2 * p];
        m[p] = k + __shfl_xor_sync(0xffffffffu, s, 16);
    }
    float n[2];
    #pragma unroll
    for (int p = 0; p < 2; p++) {
        float s = (lane & 8) ? m[2 * p]     : m[2 * p + 1];
        float k = (lane & 8) ? m[2 * p + 1] : m[2 * p];
        n[p] = k + __shfl_xor_sync(0xffffffffu, s, 8);
    }
    float s = (lane & 4) ? n[0] : n[1];
    float k = (lane & 4) ? n[1] : n[0];
    float o = k + __shfl_xor_sync(0xffffffffu, s, 4);
    o += __shfl_xor_sync(0xffffffffu, o, 2);
    o += __shfl_xor_sync(0xffffffffu, o, 1);
    return o;
}

// ---------------- precompute: A mma fragments (hi/lo) + bsT ----------------
__global__ void precompute_kernel(const float* __restrict__ bs,
                                  const float* __restrict__ Vs) {
    int e = blockIdx.x * blockDim.x + threadIdx.x;   // 0..4095
    if (e < 2048) {
        int mt = e >> 9, ks = (e >> 7) & 3, lane = (e >> 2) & 31, q = e & 3;
        int row = 16 * mt + (lane >> 2) + (q & 1) * 8;
        int col = 16 * ks + (lane & 3) * 2 + ((q >> 1) & 1) * 8;
        float v0 = Vs[row * 64 + col];
        float v1 = Vs[row * 64 + col + 1];
        float r0, r1;
        uint32_t hw = pack_hi(v0, v1, r0, r1);
        g_AfHi[e] = hw;
        g_AfLo[e] = pack_lo(r0, r1);
    }
    {
        int i = e >> 6, j = e & 63;
        g_bsT[e] = bs[j * 64 + i];
    }
}

// ---------------- main kernel: 1 batch element per block ----------------
__global__ __launch_bounds__(TPB, 4)
void adj_attn_mma(const float* __restrict__ x,
                  const float* __restrict__ W1,
                  const float* __restrict__ W2,
                  const float* __restrict__ W3,
                  float* __restrict__ out) {
    __shared__ __align__(16) __nv_bfloat16 tHiS[64 * PSTR];   // tT[n][j] hi
    __shared__ __align__(16) __nv_bfloat16 tLoS[64 * PSTR];   // tT[n][j] lo
    __shared__ float lhsS[NODES];
    __shared__ float rhsS[NODES];
    __shared__ float redS[8];

    const int tid  = threadIdx.x;
    const int lane = tid & 31;
    const int w    = tid >> 5;

    // ---- lhs/rhs dot products: warp w handles rows 8w..8w+7 ----
    const float w1   = *W1;
    const float4 w2a = *(const float4*)(W2 + 4 * lane);
    const float4 w2b = *(const float4*)(W2 + 128 + 4 * lane);
    const float4 w3a = *(const float4*)(W3 + 4 * lane);
    const float4 w3b = *(const float4*)(W3 + 128 + 4 * lane);
    const float* xb  = x + (size_t)blockIdx.x * (NODES * DIM);

    float a2[8], a3[8];
    #pragma unroll
    for (int r = 0; r < 8; r++) {
        const float* xr = xb + ((w << 3) + r) * DIM;
        float4 u = *(const float4*)(xr + (lane << 2));
        float4 v = *(const float4*)(xr + 128 + (lane << 2));
        a2[r] = u.x * w2a.x + u.y * w2a.y + u.z * w2a.z + u.w * w2a.w
              + v.x * w2b.x + v.y * w2b.y + v.z * w2b.z + v.w * w2b.w;
        a3[r] = u.x * w3a.x + u.y * w3a.y + u.z * w3a.z + u.w * w3a.w
              + v.x * w3b.x + v.y * w3b.y + v.z * w3b.z + v.w * w3b.w;
    }
    float s2 = reduce8(a2, lane);
    float s3 = reduce8(a3, lane);
    if ((lane & 3) == 0) {
        int R = 4 * ((lane >> 2) & 1) + 2 * ((lane >> 3) & 1) + ((lane >> 4) & 1);
        lhsS[(w << 3) + R] = w1 * s2;
        rhsS[(w << 3) + R] = s3;
    }
    __syncthreads();

    // ---- build tT[n][j] = tanh(lhs[j]*rhs[n] + bsT[n][j]) as bf16 hi/lo ----
    {
        const int n  = tid >> 2;
        const int j0 = (tid & 3) * 16;
        const float rv = rhsS[n];
        #pragma unroll
        for (int c = 0; c < 2; c++) {
            const int j = j0 + c * 8;
            float4 l0 = *(const float4*)(lhsS + j);
            float4 l1 = *(const float4*)(lhsS + j + 4);
            float4 b0 = *(const float4*)(g_bsT + n * 64 + j);
            float4 b1 = *(const float4*)(g_bsT + n * 64 + j + 4);
            float tv[8];
            tv[0] = fast_tanh(fmaf(l0.x, rv, b0.x));
            tv[1] = fast_tanh(fmaf(l0.y, rv, b0.y));
            tv[2] = fast_tanh(fmaf(l0.z, rv, b0.z));
            tv[3] = fast_tanh(fmaf(l0.w, rv, b0.w));
            tv[4] = fast_tanh(fmaf(l1.x, rv, b1.x));
            tv[5] = fast_tanh(fmaf(l1.y, rv, b1.y));
            tv[6] = fast_tanh(fmaf(l1.z, rv, b1.z));
            tv[7] = fast_tanh(fmaf(l1.w, rv, b1.w));
            uint4 hw, lw;
            float r0, r1;
            hw.x = pack_hi(tv[0], tv[1], r0, r1); lw.x = pack_lo(r0, r1);
            hw.y = pack_hi(tv[2], tv[3], r0, r1); lw.y = pack_lo(r0, r1);
            hw.z = pack_hi(tv[4], tv[5], r0, r1); lw.z = pack_lo(r0, r1);
            hw.w = pack_hi(tv[6], tv[7], r0, r1); lw.w = pack_lo(r0, r1);
            *(uint4*)((char*)tHiS + (n * PSTR + j) * 2) = hw;
            *(uint4*)((char*)tLoS + (n * PSTR + j) * 2) = lw;
        }
    }
    __syncthreads();

    // ---- warp-level GEMM: warp w -> rows 16*(w>>1).., cols 32*(w&1).. ----
    const int mt = w >> 1;
    const int nh = w & 1;

    const uint32_t sTHi = smem_u32(tHiS);
    const uint32_t sTLo = smem_u32(tLoS);

    const uint32_t bOff0 = (uint32_t)(((nh * 32 + (lane & 7) + ((lane >> 4) & 1) * 8) * PSTR
                                       + ((lane >> 3) & 1) * 8) * 2);
    const uint32_t bOff1 = bOff0 + (uint32_t)(16 * PSTR * 2);

    float acc[16];
    #pragma unroll
    for (int i = 0; i < 16; i++) acc[i] = 0.0f;

    const uint4* fHi = (const uint4*)g_AfHi;   // [(mt*4+ks)*32 + lane]
    const uint4* fLo = (const uint4*)g_AfLo;

    #pragma unroll
    for (int ks = 0; ks < 4; ks++) {
        const int fidx = (mt * 4 + ks) * 32 + lane;
        uint4 ah = fHi[fidx];
        uint4 al = fLo[fidx];
        const uint32_t joff = (uint32_t)(ks * 32);
        uint32_t bh0, bh1, bh2, bh3, bh4, bh5, bh6, bh7;
        uint32_t bl0, bl1, bl2, bl3, bl4, bl5, bl6, bl7;
        ldsm_x4(bh0, bh1, bh2, bh3, sTHi + bOff0 + joff);
        ldsm_x4(bh4, bh5, bh6, bh7, sTHi + bOff1 + joff);
        ldsm_x4(bl0, bl1, bl2, bl3, sTLo + bOff0 + joff);
        ldsm_x4(bl4, bl5, bl6, bl7, sTLo + bOff1 + joff);
        // Ah*Bh
        mma_bf16(acc[0],  acc[1],  acc[2],  acc[3],  ah.x, ah.y, ah.z, ah.w, bh0, bh1);
        mma_bf16(acc[4],  acc[5],  acc[6],  acc[7],  ah.x, ah.y, ah.z, ah.w, bh2, bh3);
        mma_bf16(acc[8],  acc[9],  acc[10], acc[11], ah.x, ah.y, ah.z, ah.w, bh4, bh5);
        mma_bf16(acc[12], acc[13], acc[14], acc[15], ah.x, ah.y, ah.z, ah.w, bh6, bh7);
        // Ah*Bl
        mma_bf16(acc[0],  acc[1],  acc[2],  acc[3],  ah.x, ah.y, ah.z, ah.w, bl0, bl1);
        mma_bf16(acc[4],  acc[5],  acc[6],  acc[7],  ah.x, ah.y, ah.z, ah.w, bl2, bl3);
        mma_bf16(acc[8],  acc[9],  acc[10], acc[11], ah.x, ah.y, ah.z, ah.w, bl4, bl5);
        mma_bf16(acc[12], acc[13], acc[14], acc[15], ah.x, ah.y, ah.z, ah.w, bl6, bl7);
        // Al*Bh
        mma_bf16(acc[0],  acc[1],  acc[2],  acc[3],  al.x, al.y, al.z, al.w, bh0, bh1);
        mma_bf16(acc[4],  acc[5],  acc[6],  acc[7],  al.x, al.y, al.z, al.w, bh2, bh3);
        mma_bf16(acc[8],  acc[9],  acc[10], acc[11], al.x, al.y, al.z, al.w, bh4, bh5);
        mma_bf16(acc[12], acc[13], acc[14], acc[15], al.x, al.y, al.z, al.w, bh6, bh7);
    }

    // ---- softmax WITHOUT max subtraction (|s| <~ 76 -> exp finite in fp32) ----
    float lsum = 0.0f;
    #pragma unroll
    for (int i = 0; i < 16; i++) {
        acc[i] = __expf(acc[i]);
        lsum += acc[i];
    }
    #pragma unroll
    for (int sft = 16; sft > 0; sft >>= 1)
        lsum += __shfl_xor_sync(0xffffffffu, lsum, sft);
    if (lane == 0) redS[w] = lsum;
    __syncthreads();
    float tot = redS[0];
    #pragma unroll
    for (int i = 1; i < 8; i++) tot += redS[i];
    const float inv = 1.0f / tot;

    // ---- store: rows {16mt+lane/4, +8}, cols 32nh + g*8 + (lane%4)*2 ----
    float* ob = out + (size_t)blockIdx.x * (NODES * NODES);
    const int row0 = 16 * mt + (lane >> 2);
    const int col0 = 32 * nh + (lane & 3) * 2;
    #pragma unroll
    for (int g = 0; g < 4; g++) {
        float2 o;
        o.x = acc[g * 4 + 0] * inv;
        o.y = acc[g * 4 + 1] * inv;
        *(float2*)(ob + row0 * NODES + col0 + g * 8) = o;
        o.x = acc[g * 4 + 2] * inv;
        o.y = acc[g * 4 + 3] * inv;
        *(float2*)(ob + (row0 + 8) * NODES + col0 + g * 8) = o;
    }
}

extern "C" void kernel_launch(void* const* d_in, const int* in_sizes, int n_in,
                              void* d_out, int out_size) {
    const float* x  = (const float*)d_in[0];
    const float* W1 = (const float*)d_in[1];
    const float* W2 = (const float*)d_in[2];
    const float* W3 = (const float*)d_in[3];
    const float* bs = (const float*)d_in[4];
    const float* Vs = (const float*)d_in[5];
    float* out = (float*)d_out;

    const int B = in_sizes[0] / (NODES * DIM);   // 4096
    precompute_kernel<<<16, 256>>>(bs, Vs);
    adj_attn_mma<<<B, TPB>>>(x, W1, W2, W3, out);
}